// round 4
// baseline (speedup 1.0000x reference)
#include <cuda_runtime.h>

#define N_NODES 100000
#define N_EDGES 3200000
#define G_GROUPS 128
#define F_IN 9
#define H_DIM 64

// Scratch (__device__ globals; no allocation allowed).
__device__ __align__(16) float g_h1[N_NODES * H_DIM];   // hidden after conv1
__device__ __align__(16) float g_agg[N_NODES * H_DIM];  // aggregation (pass1 uses stride-12)
__device__ __align__(16) float g_xp[N_NODES * 12];      // x padded to 48B rows
__device__ int   g_deg[N_NODES];
__device__ int   g_off[N_NODES + 1];
__device__ int   g_cur[N_NODES];
__device__ __align__(8) int2 g_csr[N_EDGES];            // (src, edge_attr bits) per edge, bucketed by dst
__device__ __align__(16) float g_pi[N_NODES];
__device__ __align__(16) float g_texp[G_GROUPS];

// ---------------------------------------------------------------------------
// prep: zero degree counters + texp, pad x into 16B-aligned stride-12 rows.
__global__ void prep_kernel(const float* __restrict__ x) {
    int i = blockIdx.x * blockDim.x + threadIdx.x;
    if (i < G_GROUPS) g_texp[i] = 0.f;
    if (i >= N_NODES) return;
    g_deg[i] = 0;
    float4 a = make_float4(x[i*9+0], x[i*9+1], x[i*9+2], x[i*9+3]);
    float4 b = make_float4(x[i*9+4], x[i*9+5], x[i*9+6], x[i*9+7]);
    float4 c = make_float4(x[i*9+8], 0.f, 0.f, 0.f);
    float4* p = reinterpret_cast<float4*>(&g_xp[i*12]);
    p[0] = a; p[1] = b; p[2] = c;
}

// ---------------------------------------------------------------------------
__global__ void hist_kernel(const int* __restrict__ ei) {
    int e = blockIdx.x * blockDim.x + threadIdx.x;
    if (e >= N_EDGES) return;
    atomicAdd(&g_deg[__ldg(&ei[N_EDGES + e])], 1);
}

// ---------------------------------------------------------------------------
// Single-block exclusive scan of g_deg -> g_off (and g_cur copy). 1024 threads.
__global__ void scan_kernel() {
    const int T = 1024;
    const int CH = (N_NODES + T - 1) / T;  // 98
    int tid = threadIdx.x;
    int start = tid * CH;
    int end = min(start + CH, N_NODES);

    int local = 0;
    for (int i = start; i < end; i++) local += g_deg[i];

    __shared__ int sh[T];
    sh[tid] = local;
    __syncthreads();
    for (int off = 1; off < T; off <<= 1) {
        int v = (tid >= off) ? sh[tid - off] : 0;
        __syncthreads();
        sh[tid] += v;
        __syncthreads();
    }
    int run = sh[tid] - local;  // exclusive prefix

    for (int i = start; i < end; i++) {
        g_off[i] = run;
        g_cur[i] = run;
        run += g_deg[i];
    }
    if (end == N_NODES && start < N_NODES) g_off[N_NODES] = run;
    if (tid == T - 1 && start >= N_NODES) g_off[N_NODES] = sh[T - 1];
}

// ---------------------------------------------------------------------------
__global__ void scatter_kernel(const int* __restrict__ ei,
                               const float* __restrict__ eattr) {
    int e = blockIdx.x * blockDim.x + threadIdx.x;
    if (e >= N_EDGES) return;
    int s = __ldg(&ei[e]);
    int d = __ldg(&ei[N_EDGES + e]);
    float a = __ldg(&eattr[e]);
    int pos = atomicAdd(&g_cur[d], 1);
    g_csr[pos] = make_int2(s, __float_as_int(a));
}

// ---------------------------------------------------------------------------
// Edge pass 1 (gather): warp per dst node. Each lane handles a subset of the
// node's edges, accumulates 9-float message sums, butterfly-reduces, lane0 writes.
__global__ void edge1_gather(const float* __restrict__ We1,
                             const float* __restrict__ be1) {
    int gt = blockIdx.x * blockDim.x + threadIdx.x;
    int n = gt >> 5;
    int lane = gt & 31;
    if (n >= N_NODES) return;

    float w[9], b[9];
#pragma unroll
    for (int f = 0; f < 9; f++) { w[f] = __ldg(&We1[f]); b[f] = __ldg(&be1[f]); }

    int beg = __ldg(&g_off[n]);
    int end = __ldg(&g_off[n + 1]);

    float acc[9];
#pragma unroll
    for (int f = 0; f < 9; f++) acc[f] = 0.f;

    for (int j = beg + lane; j < end; j += 32) {
        int2 sa = __ldg(&g_csr[j]);
        float a = __int_as_float(sa.y);
        const float4* xr = reinterpret_cast<const float4*>(&g_xp[sa.x * 12]);
        float4 x0 = __ldg(xr + 0);
        float4 x1 = __ldg(xr + 1);
        float4 x2 = __ldg(xr + 2);
        acc[0] += fmaxf(x0.x + fmaf(a, w[0], b[0]), 0.f);
        acc[1] += fmaxf(x0.y + fmaf(a, w[1], b[1]), 0.f);
        acc[2] += fmaxf(x0.z + fmaf(a, w[2], b[2]), 0.f);
        acc[3] += fmaxf(x0.w + fmaf(a, w[3], b[3]), 0.f);
        acc[4] += fmaxf(x1.x + fmaf(a, w[4], b[4]), 0.f);
        acc[5] += fmaxf(x1.y + fmaf(a, w[5], b[5]), 0.f);
        acc[6] += fmaxf(x1.z + fmaf(a, w[6], b[6]), 0.f);
        acc[7] += fmaxf(x1.w + fmaf(a, w[7], b[7]), 0.f);
        acc[8] += fmaxf(x2.x + fmaf(a, w[8], b[8]), 0.f);
    }
#pragma unroll
    for (int f = 0; f < 9; f++) {
#pragma unroll
        for (int o = 16; o > 0; o >>= 1)
            acc[f] += __shfl_xor_sync(0xffffffffu, acc[f], o);
    }
    if (lane == 0) {
        float* dst = &g_agg[n * 12];
#pragma unroll
        for (int f = 0; f < 9; f++) dst[f] = acc[f];
    }
}

// ---------------------------------------------------------------------------
// Node MLP 1: z = x + agg; h1 = relu(relu(z@W1a+b1a)@W1b+b1b)
__global__ void mlp1_kernel(const float* __restrict__ x,
                            const float* __restrict__ W1a, const float* __restrict__ b1a,
                            const float* __restrict__ W1b, const float* __restrict__ b1b) {
    __shared__ __align__(16) float sWa[F_IN * H_DIM];
    __shared__ __align__(16) float sWb[H_DIM * H_DIM];
    __shared__ __align__(16) float sba[H_DIM];
    __shared__ __align__(16) float sbb[H_DIM];
    int tid = threadIdx.x;
    for (int i = tid; i < F_IN * H_DIM; i += blockDim.x) sWa[i] = W1a[i];
    for (int i = tid; i < H_DIM * H_DIM; i += blockDim.x) sWb[i] = W1b[i];
    if (tid < H_DIM) { sba[tid] = b1a[tid]; sbb[tid] = b1b[tid]; }
    __syncthreads();

    int n = blockIdx.x * blockDim.x + tid;
    if (n >= N_NODES) return;

    float z[F_IN];
#pragma unroll
    for (int f = 0; f < F_IN; f++) z[f] = x[n * 9 + f] + g_agg[n * 12 + f];

    float t[H_DIM];
#pragma unroll
    for (int j = 0; j < H_DIM; j += 4) {
        float4 acc = *reinterpret_cast<float4*>(&sba[j]);
#pragma unroll
        for (int f = 0; f < F_IN; f++) {
            float4 w = *reinterpret_cast<float4*>(&sWa[f * H_DIM + j]);
            acc.x = fmaf(z[f], w.x, acc.x);
            acc.y = fmaf(z[f], w.y, acc.y);
            acc.z = fmaf(z[f], w.z, acc.z);
            acc.w = fmaf(z[f], w.w, acc.w);
        }
        t[j + 0] = fmaxf(acc.x, 0.f);
        t[j + 1] = fmaxf(acc.y, 0.f);
        t[j + 2] = fmaxf(acc.z, 0.f);
        t[j + 3] = fmaxf(acc.w, 0.f);
    }

    for (int j = 0; j < H_DIM; j += 4) {
        float4 acc = *reinterpret_cast<float4*>(&sbb[j]);
#pragma unroll
        for (int k = 0; k < H_DIM; k++) {
            float4 w = *reinterpret_cast<float4*>(&sWb[k * H_DIM + j]);
            acc.x = fmaf(t[k], w.x, acc.x);
            acc.y = fmaf(t[k], w.y, acc.y);
            acc.z = fmaf(t[k], w.z, acc.z);
            acc.w = fmaf(t[k], w.w, acc.w);
        }
        float4 o;
        o.x = fmaxf(acc.x, 0.f);
        o.y = fmaxf(acc.y, 0.f);
        o.z = fmaxf(acc.z, 0.f);
        o.w = fmaxf(acc.w, 0.f);
        *reinterpret_cast<float4*>(&g_h1[n * H_DIM + j]) = o;
    }
}

// ---------------------------------------------------------------------------
// Edge pass 2 (gather): 16 threads per dst node, each owns a float4 feature
// chunk, loops the node's edge list. No atomics.
__global__ void edge2_gather(const float* __restrict__ We2,
                             const float* __restrict__ be2) {
    int gt = blockIdx.x * blockDim.x + threadIdx.x;
    int n = gt >> 4;
    int c = (gt & 15) << 2;
    if (n >= N_NODES) return;

    float4 w = __ldg(reinterpret_cast<const float4*>(&We2[c]));
    float4 b = __ldg(reinterpret_cast<const float4*>(&be2[c]));
    int beg = __ldg(&g_off[n]);
    int end = __ldg(&g_off[n + 1]);

    float4 acc = make_float4(0.f, 0.f, 0.f, 0.f);
    for (int j = beg; j < end; j++) {
        int2 sa = __ldg(&g_csr[j]);
        float a = __int_as_float(sa.y);
        float4 h = __ldg(reinterpret_cast<const float4*>(&g_h1[sa.x * H_DIM + c]));
        acc.x += fmaxf(h.x + fmaf(a, w.x, b.x), 0.f);
        acc.y += fmaxf(h.y + fmaf(a, w.y, b.y), 0.f);
        acc.z += fmaxf(h.z + fmaf(a, w.z, b.z), 0.f);
        acc.w += fmaxf(h.w + fmaf(a, w.w, b.w), 0.f);
    }
    *reinterpret_cast<float4*>(&g_agg[n * H_DIM + c]) = acc;
}

// ---------------------------------------------------------------------------
// Node MLP 2 + readout head + group segment-sum of expenses.
__global__ void mlp2_kernel(const float* __restrict__ W2a, const float* __restrict__ b2a,
                            const float* __restrict__ W2b, const float* __restrict__ b2b,
                            const float* __restrict__ Wr1, const float* __restrict__ br1,
                            const float* __restrict__ Wr2, const float* __restrict__ br2,
                            const int* __restrict__ batch,
                            const int* __restrict__ term,
                            const float* __restrict__ c_cost) {
    __shared__ __align__(16) float sWa[H_DIM * H_DIM];
    __shared__ __align__(16) float sWb[H_DIM * H_DIM];
    __shared__ __align__(16) float sWr1[H_DIM * 32];
    __shared__ __align__(16) float sba[H_DIM];
    __shared__ __align__(16) float sbb[H_DIM];
    __shared__ __align__(16) float sbr1[32];
    __shared__ __align__(16) float sWr2[32];
    __shared__ float sbr2;
    int tid = threadIdx.x;
    for (int i = tid; i < H_DIM * H_DIM; i += blockDim.x) { sWa[i] = W2a[i]; sWb[i] = W2b[i]; }
    for (int i = tid; i < H_DIM * 32; i += blockDim.x) sWr1[i] = Wr1[i];
    if (tid < H_DIM) { sba[tid] = b2a[tid]; sbb[tid] = b2b[tid]; }
    if (tid < 32) { sbr1[tid] = br1[tid]; sWr2[tid] = Wr2[tid]; }
    if (tid == 0) sbr2 = br2[0];
    __syncthreads();

    int n = blockIdx.x * blockDim.x + tid;
    if (n >= N_NODES) return;

    float z[H_DIM];
#pragma unroll
    for (int k = 0; k < H_DIM; k += 4) {
        float4 hv = *reinterpret_cast<const float4*>(&g_h1[n * H_DIM + k]);
        float4 av = *reinterpret_cast<const float4*>(&g_agg[n * H_DIM + k]);
        z[k + 0] = hv.x + av.x;
        z[k + 1] = hv.y + av.y;
        z[k + 2] = hv.z + av.z;
        z[k + 3] = hv.w + av.w;
    }

    float t[H_DIM];
    for (int j = 0; j < H_DIM; j += 4) {
        float4 acc = *reinterpret_cast<float4*>(&sba[j]);
#pragma unroll
        for (int k = 0; k < H_DIM; k++) {
            float4 w = *reinterpret_cast<float4*>(&sWa[k * H_DIM + j]);
            acc.x = fmaf(z[k], w.x, acc.x);
            acc.y = fmaf(z[k], w.y, acc.y);
            acc.z = fmaf(z[k], w.z, acc.z);
            acc.w = fmaf(z[k], w.w, acc.w);
        }
        t[j + 0] = fmaxf(acc.x, 0.f);
        t[j + 1] = fmaxf(acc.y, 0.f);
        t[j + 2] = fmaxf(acc.z, 0.f);
        t[j + 3] = fmaxf(acc.w, 0.f);
    }

    // reuse z[] as h2
    for (int j = 0; j < H_DIM; j += 4) {
        float4 acc = *reinterpret_cast<float4*>(&sbb[j]);
#pragma unroll
        for (int k = 0; k < H_DIM; k++) {
            float4 w = *reinterpret_cast<float4*>(&sWb[k * H_DIM + j]);
            acc.x = fmaf(t[k], w.x, acc.x);
            acc.y = fmaf(t[k], w.y, acc.y);
            acc.z = fmaf(t[k], w.z, acc.z);
            acc.w = fmaf(t[k], w.w, acc.w);
        }
        z[j + 0] = fmaxf(acc.x, 0.f);
        z[j + 1] = fmaxf(acc.y, 0.f);
        z[j + 2] = fmaxf(acc.z, 0.f);
        z[j + 3] = fmaxf(acc.w, 0.f);
    }

    // readout: r = relu(h2 @ Wr1 + br1) [32]; p = r @ Wr2 + br2
    float r[32];
    for (int j = 0; j < 32; j += 4) {
        float4 acc = *reinterpret_cast<float4*>(&sbr1[j]);
#pragma unroll
        for (int k = 0; k < H_DIM; k++) {
            float4 w = *reinterpret_cast<float4*>(&sWr1[k * 32 + j]);
            acc.x = fmaf(z[k], w.x, acc.x);
            acc.y = fmaf(z[k], w.y, acc.y);
            acc.z = fmaf(z[k], w.z, acc.z);
            acc.w = fmaf(z[k], w.w, acc.w);
        }
        r[j + 0] = fmaxf(acc.x, 0.f);
        r[j + 1] = fmaxf(acc.y, 0.f);
        r[j + 2] = fmaxf(acc.z, 0.f);
        r[j + 3] = fmaxf(acc.w, 0.f);
    }
    float p = sbr2;
#pragma unroll
    for (int k = 0; k < 32; k++) p = fmaf(r[k], sWr2[k], p);

    float pi = 1.f / (1.f + expf(-p));
    if (term[n] != 0) pi = 0.f;
    g_pi[n] = pi;
    atomicAdd(&g_texp[batch[n]], pi * c_cost[n]);
}

// ---------------------------------------------------------------------------
__global__ void final_kernel(const int* __restrict__ batch,
                             const float* __restrict__ B_total,
                             float* __restrict__ out) {
    int n = blockIdx.x * blockDim.x + threadIdx.x;
    if (n >= N_NODES) return;
    int b = batch[n];
    float ratio = fminf(B_total[b] / (g_texp[b] + 1e-12f), 1.f);
    out[n] = g_pi[n] * ratio;
}

// ---------------------------------------------------------------------------
extern "C" void kernel_launch(void* const* d_in, const int* in_sizes, int n_in,
                              void* d_out, int out_size) {
    const float* x       = (const float*)d_in[0];
    const int*   ei      = (const int*)d_in[1];
    const float* eattr   = (const float*)d_in[2];
    const int*   batch   = (const int*)d_in[3];
    const float* B_total = (const float*)d_in[4];
    const int*   term    = (const int*)d_in[5];
    const float* c_cost  = (const float*)d_in[6];
    const float* We1 = (const float*)d_in[7];
    const float* be1 = (const float*)d_in[8];
    const float* W1a = (const float*)d_in[9];
    const float* b1a = (const float*)d_in[10];
    const float* W1b = (const float*)d_in[11];
    const float* b1b = (const float*)d_in[12];
    const float* We2 = (const float*)d_in[13];
    const float* be2 = (const float*)d_in[14];
    const float* W2a = (const float*)d_in[15];
    const float* b2a = (const float*)d_in[16];
    const float* W2b = (const float*)d_in[17];
    const float* b2b = (const float*)d_in[18];
    const float* Wr1 = (const float*)d_in[19];
    const float* br1 = (const float*)d_in[20];
    const float* Wr2 = (const float*)d_in[21];
    const float* br2 = (const float*)d_in[22];
    float* out = (float*)d_out;

    const int NB_NODE = (N_NODES + 255) / 256;
    const int NB_EDGE = (N_EDGES + 255) / 256;

    prep_kernel<<<NB_NODE, 256>>>(x);
    hist_kernel<<<NB_EDGE, 256>>>(ei);
    scan_kernel<<<1, 1024>>>();
    scatter_kernel<<<NB_EDGE, 256>>>(ei, eattr);
    edge1_gather<<<(N_NODES * 32 + 255) / 256, 256>>>(We1, be1);
    mlp1_kernel<<<NB_NODE, 256>>>(x, W1a, b1a, W1b, b1b);
    edge2_gather<<<(N_NODES * 16 + 255) / 256, 256>>>(We2, be2);
    mlp2_kernel<<<NB_NODE, 256>>>(W2a, b2a, W2b, b2b, Wr1, br1, Wr2, br2,
                                  batch, term, c_cost);
    final_kernel<<<NB_NODE, 256>>>(batch, B_total, out);
}